// round 1
// baseline (speedup 1.0000x reference)
#include <cuda_runtime.h>
#include <cuda_bf16.h>
#include <cstdio>

#define NN 50000
#define EE 800000
#define HH 128
#define GG 512

// ---------------- device scratch (no allocations allowed) ----------------
__device__ float d_x[NN * HH];
__device__ float d_y[NN * HH];
__device__ float d_agg[NN * HH];
__device__ int   d_count[NN];
__device__ int   d_rowptr[NN + 1];
__device__ int   d_cursor[NN];
__device__ int   d_csrsrc[EE];
__device__ float d_deginv[NN];
__device__ int   d_start[GG + 1];
__device__ float d_g[GG * HH];

// ---------------- helpers ----------------
__device__ __forceinline__ float4 add4(float4 a, float4 b) {
    return make_float4(a.x + b.x, a.y + b.y, a.z + b.z, a.w + b.w);
}

// ---------------- embedding gather: x[n] = z_emb[z[n]] ----------------
__global__ void embed_kernel(const int* __restrict__ z,
                             const float* __restrict__ z_emb,
                             float* __restrict__ x) {
    int idx = blockIdx.x * blockDim.x + threadIdx.x;   // over NN*32 float4s
    if (idx >= NN * 32) return;
    int n  = idx >> 5;
    int c4 = idx & 31;
    int zn = z[n];
    const float4* src = reinterpret_cast<const float4*>(z_emb) + (size_t)zn * 32 + c4;
    reinterpret_cast<float4*>(x)[idx] = *src;
}

__global__ void zero_count_kernel(int* __restrict__ count) {
    int i = blockIdx.x * blockDim.x + threadIdx.x;
    if (i < NN) count[i] = 0;
}

__global__ void hist_kernel(const int* __restrict__ dst, int* __restrict__ count) {
    int e = blockIdx.x * blockDim.x + threadIdx.x;
    if (e < EE) atomicAdd(&count[dst[e]], 1);
}

// single-block scan (1024 threads, Hillis-Steele in shared, sequential carry)
__global__ void scan_kernel(const int* __restrict__ count,
                            int* __restrict__ rowptr,
                            int* __restrict__ cursor,
                            float* __restrict__ deginv) {
    __shared__ int s[1024];
    int tid = threadIdx.x;
    int carry = 0;
    for (int base = 0; base < NN; base += 1024) {
        int i = base + tid;
        int v = (i < NN) ? count[i] : 0;
        s[tid] = v;
        __syncthreads();
        #pragma unroll
        for (int off = 1; off < 1024; off <<= 1) {
            int t = (tid >= off) ? s[tid - off] : 0;
            __syncthreads();
            s[tid] += t;
            __syncthreads();
        }
        int incl = s[tid];
        int excl = incl - v + carry;
        if (i < NN) {
            rowptr[i] = excl;
            cursor[i] = excl;
            deginv[i] = 1.0f / (float)max(v, 1);
        }
        carry += s[1023];
        __syncthreads();
    }
    if (tid == 0) rowptr[NN] = carry;   // == EE
}

__global__ void fill_csr_kernel(const int* __restrict__ src,
                                const int* __restrict__ dst,
                                int* __restrict__ cursor,
                                int* __restrict__ csrsrc) {
    int e = blockIdx.x * blockDim.x + threadIdx.x;
    if (e >= EE) return;
    int d = dst[e];
    int pos = atomicAdd(&cursor[d], 1);
    csrsrc[pos] = src[e];
}

// ---------------- mean aggregation: warp per destination node ----------------
__global__ void aggregate_kernel(const float* __restrict__ x,
                                 const int* __restrict__ rowptr,
                                 const int* __restrict__ csrsrc,
                                 const float* __restrict__ deginv,
                                 float* __restrict__ out) {
    int node = blockIdx.x * blockDim.y + threadIdx.y;
    if (node >= NN) return;
    int lane = threadIdx.x;
    int beg = rowptr[node];
    int end = rowptr[node + 1];
    float4 a0 = make_float4(0, 0, 0, 0);
    float4 a1 = make_float4(0, 0, 0, 0);
    int j = beg;
    for (; j + 1 < end; j += 2) {
        int s0 = __ldg(&csrsrc[j]);
        int s1 = __ldg(&csrsrc[j + 1]);
        float4 v0 = *reinterpret_cast<const float4*>(x + (size_t)s0 * HH + lane * 4);
        float4 v1 = *reinterpret_cast<const float4*>(x + (size_t)s1 * HH + lane * 4);
        a0 = add4(a0, v0);
        a1 = add4(a1, v1);
    }
    if (j < end) {
        int s0 = __ldg(&csrsrc[j]);
        float4 v0 = *reinterpret_cast<const float4*>(x + (size_t)s0 * HH + lane * 4);
        a0 = add4(a0, v0);
    }
    float di = deginv[node];
    float4 acc = add4(a0, a1);
    acc.x *= di; acc.y *= di; acc.z *= di; acc.w *= di;
    *reinterpret_cast<float4*>(out + (size_t)node * HH + lane * 4) = acc;
}

// ---------------- fused SAGE linear: y = aggs@Wl + x@Wr + bl (opt relu) -----
// K=256 GEMM: A = [aggs | x] (N x 256), B = [Wl ; Wr] (256 x 128)
#define BM 128
#define BN 128
#define BK 16
#define TM 8
#define TN 8

__global__ __launch_bounds__(256)
void sage_gemm_kernel(const float* __restrict__ A0,   // aggs [N,128]
                      const float* __restrict__ A1,   // x    [N,128]
                      const float* __restrict__ Wl,
                      const float* __restrict__ Wr,
                      const float* __restrict__ bias,
                      float* __restrict__ out,
                      int nrows, int do_relu) {
    __shared__ float As[BK][BM + 4];
    __shared__ float Bs[BK][BN];
    int block_row = blockIdx.x * BM;
    int tid = threadIdx.x;
    int tr = tid >> 4;          // 0..15
    int tc = tid & 15;          // 0..15

    float acc[TM][TN];
    #pragma unroll
    for (int m = 0; m < TM; m++)
        #pragma unroll
        for (int n = 0; n < TN; n++) acc[m][n] = 0.0f;

    for (int kt = 0; kt < 256; kt += BK) {
        const float* Asrc = (kt < 128) ? A0 : A1;
        const float* Wsrc = (kt < 128) ? Wl : Wr;
        int kcol = kt & 127;

        // load A tile (128 rows x 16 cols), store transposed
        #pragma unroll
        for (int i = 0; i < 2; i++) {
            int idx = tid + i * 256;          // 0..511 float4s
            int r  = idx >> 2;                // 0..127
            int c4 = (idx & 3) * 4;           // 0,4,8,12
            int grow = block_row + r;
            float4 v = make_float4(0, 0, 0, 0);
            if (grow < nrows)
                v = *reinterpret_cast<const float4*>(Asrc + (size_t)grow * HH + kcol + c4);
            As[c4 + 0][r] = v.x;
            As[c4 + 1][r] = v.y;
            As[c4 + 2][r] = v.z;
            As[c4 + 3][r] = v.w;
        }
        // load B tile (16 rows x 128 cols)
        #pragma unroll
        for (int i = 0; i < 2; i++) {
            int idx = tid + i * 256;          // 0..511 float4s
            int r  = idx >> 5;                // 0..15
            int c4 = (idx & 31) * 4;
            float4 v = *reinterpret_cast<const float4*>(Wsrc + (size_t)(kcol + r) * HH + c4);
            *reinterpret_cast<float4*>(&Bs[r][c4]) = v;
        }
        __syncthreads();

        #pragma unroll
        for (int k = 0; k < BK; k++) {
            float a[TM], b[TN];
            #pragma unroll
            for (int m = 0; m < TM; m++) a[m] = As[k][tr * TM + m];
            #pragma unroll
            for (int n = 0; n < TN; n++) b[n] = Bs[k][tc * TN + n];
            #pragma unroll
            for (int m = 0; m < TM; m++)
                #pragma unroll
                for (int n = 0; n < TN; n++)
                    acc[m][n] = fmaf(a[m], b[n], acc[m][n]);
        }
        __syncthreads();
    }

    #pragma unroll
    for (int m = 0; m < TM; m++) {
        int grow = block_row + tr * TM + m;
        if (grow >= nrows) continue;
        #pragma unroll
        for (int n = 0; n < TN; n++) {
            int c = tc * TN + n;
            float v = acc[m][n] + bias[c];
            if (do_relu) v = fmaxf(v, 0.0f);
            out[(size_t)grow * HH + c] = v;
        }
    }
}

// ---------------- pooling: batch is sorted -> binary-search boundaries ------
__global__ void graph_starts_kernel(const int* __restrict__ batch, int* __restrict__ start) {
    int b = blockIdx.x * blockDim.x + threadIdx.x;
    if (b > GG) return;
    if (b == GG) { start[GG] = NN; return; }
    int lo = 0, hi = NN;
    while (lo < hi) {
        int mid = (lo + hi) >> 1;
        if (batch[mid] < b) lo = mid + 1; else hi = mid;
    }
    start[b] = lo;
}

__global__ void pool_kernel(const float* __restrict__ x,
                            const int* __restrict__ start,
                            float* __restrict__ g) {
    int b = blockIdx.x;
    int s = start[b], e = start[b + 1];
    int lane = threadIdx.x;   // 0..31
    int w = threadIdx.y;      // 0..7
    float4 acc = make_float4(0, 0, 0, 0);
    for (int n = s + w; n < e; n += 8) {
        float4 v = *reinterpret_cast<const float4*>(x + (size_t)n * HH + lane * 4);
        acc = add4(acc, v);
    }
    __shared__ float4 sh[8][32];
    sh[w][lane] = acc;
    __syncthreads();
    if (w == 0) {
        float4 t = sh[0][lane];
        #pragma unroll
        for (int i = 1; i < 8; i++) t = add4(t, sh[i][lane]);
        *reinterpret_cast<float4*>(g + (size_t)b * HH + lane * 4) = t;
    }
}

// ---------------- final MLP: out[b] = relu(g@W1+b1)@W2 + b2 ----------------
__global__ void mlp_kernel(const float* __restrict__ g,
                           const float* __restrict__ W1,
                           const float* __restrict__ b1,
                           const float* __restrict__ W2,
                           const float* __restrict__ b2,
                           float* __restrict__ out) {
    int b = blockIdx.x;
    int t = threadIdx.x;   // 0..127
    __shared__ float gs[HH];
    gs[t] = g[(size_t)b * HH + t];
    __syncthreads();
    float acc = 0.0f;
    #pragma unroll 8
    for (int k = 0; k < HH; k++)
        acc = fmaf(gs[k], W1[(size_t)k * HH + t], acc);
    float h = fmaxf(acc + b1[t], 0.0f);
    float p = h * W2[t];
    #pragma unroll
    for (int off = 16; off > 0; off >>= 1)
        p += __shfl_xor_sync(0xFFFFFFFFu, p, off);
    __shared__ float ws[4];
    if ((t & 31) == 0) ws[t >> 5] = p;
    __syncthreads();
    if (t == 0) out[b] = ws[0] + ws[1] + ws[2] + ws[3] + b2[0];
}

// ---------------- launch ----------------
extern "C" void kernel_launch(void* const* d_in, const int* in_sizes, int n_in,
                              void* d_out, int out_size) {
    const int*   z     = (const int*)d_in[0];
    const int*   ei    = (const int*)d_in[1];    // [2,E] row-major: src then dst
    const int*   batch = (const int*)d_in[2];
    const float* z_emb = (const float*)d_in[3];
    const float* Wl[3] = {(const float*)d_in[4], (const float*)d_in[7], (const float*)d_in[10]};
    const float* bl[3] = {(const float*)d_in[5], (const float*)d_in[8], (const float*)d_in[11]};
    const float* Wr[3] = {(const float*)d_in[6], (const float*)d_in[9], (const float*)d_in[12]};
    const float* W1 = (const float*)d_in[13];
    const float* b1 = (const float*)d_in[14];
    const float* W2 = (const float*)d_in[15];
    const float* b2 = (const float*)d_in[16];
    float* out = (float*)d_out;

    float *x, *y, *agg, *deginv, *g;
    int *count, *rowptr, *cursor, *csrsrc, *start;
    cudaGetSymbolAddress((void**)&x,      d_x);
    cudaGetSymbolAddress((void**)&y,      d_y);
    cudaGetSymbolAddress((void**)&agg,    d_agg);
    cudaGetSymbolAddress((void**)&deginv, d_deginv);
    cudaGetSymbolAddress((void**)&g,      d_g);
    cudaGetSymbolAddress((void**)&count,  d_count);
    cudaGetSymbolAddress((void**)&rowptr, d_rowptr);
    cudaGetSymbolAddress((void**)&cursor, d_cursor);
    cudaGetSymbolAddress((void**)&csrsrc, d_csrsrc);
    cudaGetSymbolAddress((void**)&start,  d_start);

    const int* src = ei;
    const int* dst = ei + EE;

    embed_kernel<<<(NN * 32 + 255) / 256, 256>>>(z, z_emb, x);
    zero_count_kernel<<<(NN + 255) / 256, 256>>>(count);
    hist_kernel<<<(EE + 255) / 256, 256>>>(dst, count);
    scan_kernel<<<1, 1024>>>(count, rowptr, cursor, deginv);
    fill_csr_kernel<<<(EE + 255) / 256, 256>>>(src, dst, cursor, csrsrc);
    graph_starts_kernel<<<3, 256>>>(batch, start);

    float* cur = x;
    float* nxt = y;
    for (int l = 0; l < 3; l++) {
        aggregate_kernel<<<(NN + 7) / 8, dim3(32, 8)>>>(cur, rowptr, csrsrc, deginv, agg);
        sage_gemm_kernel<<<(NN + BM - 1) / BM, 256>>>(agg, cur, Wl[l], Wr[l], bl[l], nxt, NN, (l < 2) ? 1 : 0);
        float* tmp = cur; cur = nxt; nxt = tmp;
    }

    pool_kernel<<<GG, dim3(32, 8)>>>(cur, start, g);
    mlp_kernel<<<GG, 128>>>(g, W1, b1, W2, b2, out);
}

// round 2
// speedup vs baseline: 1.1476x; 1.1476x over previous
#include <cuda_runtime.h>
#include <cuda_bf16.h>
#include <cstdio>

#define NN 50000
#define EE 800000
#define HH 128
#define GG 512
#define NBLK ((NN + 1023) / 1024)   // 49

// ---------------- device scratch (no allocations allowed) ----------------
__device__ float d_x[NN * HH];
__device__ float d_y[NN * HH];
__device__ float d_agg[NN * HH];
__device__ int   d_count[NN];
__device__ int   d_rowptr[NN + 1];
__device__ int   d_cursor[NN];
__device__ int   d_csrsrc[EE];
__device__ float d_deginv[NN];
__device__ int   d_start[GG + 1];
__device__ float d_g[GG * HH];
__device__ int   d_partial[64];

// ---------------- helpers ----------------
__device__ __forceinline__ float4 add4(float4 a, float4 b) {
    return make_float4(a.x + b.x, a.y + b.y, a.z + b.z, a.w + b.w);
}

// ---------------- embedding gather: x[n] = z_emb[z[n]] ----------------
__global__ void embed_kernel(const int* __restrict__ z,
                             const float* __restrict__ z_emb,
                             float* __restrict__ x) {
    int idx = blockIdx.x * blockDim.x + threadIdx.x;   // over NN*32 float4s
    if (idx >= NN * 32) return;
    int n  = idx >> 5;
    int c4 = idx & 31;
    int zn = z[n];
    const float4* src = reinterpret_cast<const float4*>(z_emb) + (size_t)zn * 32 + c4;
    reinterpret_cast<float4*>(x)[idx] = *src;
}

__global__ void zero_count_kernel(int* __restrict__ count) {
    int i = blockIdx.x * blockDim.x + threadIdx.x;
    if (i < NN) count[i] = 0;
}

__global__ void hist_kernel(const int* __restrict__ dst, int* __restrict__ count) {
    int e = blockIdx.x * blockDim.x + threadIdx.x;
    if (e < EE) atomicAdd(&count[dst[e]], 1);
}

// ---------------- parallel 3-phase scan ----------------
// phase 1: per-block exclusive scan (warp shuffles), emit block sums
__global__ __launch_bounds__(1024)
void scan_blocks_kernel(const int* __restrict__ count,
                        int* __restrict__ rowptr,
                        int* __restrict__ partial) {
    __shared__ int warp_sums[32];
    int gid = blockIdx.x * 1024 + threadIdx.x;
    int lane = threadIdx.x & 31;
    int wid  = threadIdx.x >> 5;
    int v = (gid < NN) ? count[gid] : 0;
    int incl = v;
    #pragma unroll
    for (int off = 1; off < 32; off <<= 1) {
        int t = __shfl_up_sync(0xFFFFFFFFu, incl, off);
        if (lane >= off) incl += t;
    }
    if (lane == 31) warp_sums[wid] = incl;
    __syncthreads();
    if (wid == 0) {
        int ws = warp_sums[lane];
        #pragma unroll
        for (int off = 1; off < 32; off <<= 1) {
            int t = __shfl_up_sync(0xFFFFFFFFu, ws, off);
            if (lane >= off) ws += t;
        }
        warp_sums[lane] = ws;
    }
    __syncthreads();
    int excl = incl - v + (wid > 0 ? warp_sums[wid - 1] : 0);
    if (gid < NN) rowptr[gid] = excl;
    if (threadIdx.x == 1023) partial[blockIdx.x] = excl + v;   // block total
}

// phase 2: one warp scans the NBLK block sums (exclusive, in-place)
__global__ void scan_partials_kernel(int* __restrict__ partial) {
    int lane = threadIdx.x;
    int carry = 0;
    for (int base = 0; base < NBLK; base += 32) {
        int i = base + lane;
        int v = (i < NBLK) ? partial[i] : 0;
        int incl = v;
        #pragma unroll
        for (int off = 1; off < 32; off <<= 1) {
            int t = __shfl_up_sync(0xFFFFFFFFu, incl, off);
            if (lane >= off) incl += t;
        }
        if (i < NBLK) partial[i] = incl - v + carry;
        carry += __shfl_sync(0xFFFFFFFFu, incl, 31);
    }
}

// phase 3: add block offsets; emit cursor + deginv
__global__ __launch_bounds__(1024)
void scan_finalize_kernel(const int* __restrict__ count,
                          const int* __restrict__ partial,
                          int* __restrict__ rowptr,
                          int* __restrict__ cursor,
                          float* __restrict__ deginv) {
    int gid = blockIdx.x * 1024 + threadIdx.x;
    if (gid < NN) {
        int r = rowptr[gid] + partial[blockIdx.x];
        rowptr[gid] = r;
        cursor[gid] = r;
        deginv[gid] = 1.0f / (float)max(count[gid], 1);
    }
    if (gid == 0) rowptr[NN] = EE;
}

__global__ void fill_csr_kernel(const int* __restrict__ src,
                                const int* __restrict__ dst,
                                int* __restrict__ cursor,
                                int* __restrict__ csrsrc) {
    int e = blockIdx.x * blockDim.x + threadIdx.x;
    if (e >= EE) return;
    int d = dst[e];
    int pos = atomicAdd(&cursor[d], 1);
    csrsrc[pos] = src[e];
}

// ---------------- mean aggregation: warp per destination node ----------------
__global__ void aggregate_kernel(const float* __restrict__ x,
                                 const int* __restrict__ rowptr,
                                 const int* __restrict__ csrsrc,
                                 const float* __restrict__ deginv,
                                 float* __restrict__ out) {
    int node = blockIdx.x * blockDim.y + threadIdx.y;
    if (node >= NN) return;
    int lane = threadIdx.x;
    int beg = rowptr[node];
    int end = rowptr[node + 1];
    float4 a0 = make_float4(0, 0, 0, 0);
    float4 a1 = make_float4(0, 0, 0, 0);
    int j = beg;
    for (; j + 1 < end; j += 2) {
        int s0 = __ldg(&csrsrc[j]);
        int s1 = __ldg(&csrsrc[j + 1]);
        float4 v0 = *reinterpret_cast<const float4*>(x + (size_t)s0 * HH + lane * 4);
        float4 v1 = *reinterpret_cast<const float4*>(x + (size_t)s1 * HH + lane * 4);
        a0 = add4(a0, v0);
        a1 = add4(a1, v1);
    }
    if (j < end) {
        int s0 = __ldg(&csrsrc[j]);
        float4 v0 = *reinterpret_cast<const float4*>(x + (size_t)s0 * HH + lane * 4);
        a0 = add4(a0, v0);
    }
    float di = deginv[node];
    float4 acc = add4(a0, a1);
    acc.x *= di; acc.y *= di; acc.z *= di; acc.w *= di;
    *reinterpret_cast<float4*>(out + (size_t)node * HH + lane * 4) = acc;
}

// ---------------- fused SAGE linear: y = aggs@Wl + x@Wr + bl (opt relu) -----
// K=256 GEMM: A = [aggs | x] (N x 256), B = [Wl ; Wr] (256 x 128)
#define BM 128
#define BN 128
#define BK 16
#define TM 8
#define TN 8

__global__ __launch_bounds__(256)
void sage_gemm_kernel(const float* __restrict__ A0,   // aggs [N,128]
                      const float* __restrict__ A1,   // x    [N,128]
                      const float* __restrict__ Wl,
                      const float* __restrict__ Wr,
                      const float* __restrict__ bias,
                      float* __restrict__ out,
                      int nrows, int do_relu) {
    __shared__ float As[BK][BM + 4];
    __shared__ float Bs[BK][BN];
    int block_row = blockIdx.x * BM;
    int tid = threadIdx.x;
    int tr = tid >> 4;          // 0..15
    int tc = tid & 15;          // 0..15

    float acc[TM][TN];
    #pragma unroll
    for (int m = 0; m < TM; m++)
        #pragma unroll
        for (int n = 0; n < TN; n++) acc[m][n] = 0.0f;

    for (int kt = 0; kt < 256; kt += BK) {
        const float* Asrc = (kt < 128) ? A0 : A1;
        const float* Wsrc = (kt < 128) ? Wl : Wr;
        int kcol = kt & 127;

        // load A tile (128 rows x 16 cols), store transposed
        #pragma unroll
        for (int i = 0; i < 2; i++) {
            int idx = tid + i * 256;          // 0..511 float4s
            int r  = idx >> 2;                // 0..127
            int c4 = (idx & 3) * 4;           // 0,4,8,12
            int grow = block_row + r;
            float4 v = make_float4(0, 0, 0, 0);
            if (grow < nrows)
                v = *reinterpret_cast<const float4*>(Asrc + (size_t)grow * HH + kcol + c4);
            As[c4 + 0][r] = v.x;
            As[c4 + 1][r] = v.y;
            As[c4 + 2][r] = v.z;
            As[c4 + 3][r] = v.w;
        }
        // load B tile (16 rows x 128 cols)
        #pragma unroll
        for (int i = 0; i < 2; i++) {
            int idx = tid + i * 256;          // 0..511 float4s
            int r  = idx >> 5;                // 0..15
            int c4 = (idx & 31) * 4;
            float4 v = *reinterpret_cast<const float4*>(Wsrc + (size_t)(kcol + r) * HH + c4);
            *reinterpret_cast<float4*>(&Bs[r][c4]) = v;
        }
        __syncthreads();

        #pragma unroll
        for (int k = 0; k < BK; k++) {
            float a[TM], b[TN];
            #pragma unroll
            for (int m = 0; m < TM; m++) a[m] = As[k][tr * TM + m];
            #pragma unroll
            for (int n = 0; n < TN; n++) b[n] = Bs[k][tc * TN + n];
            #pragma unroll
            for (int m = 0; m < TM; m++)
                #pragma unroll
                for (int n = 0; n < TN; n++)
                    acc[m][n] = fmaf(a[m], b[n], acc[m][n]);
        }
        __syncthreads();
    }

    #pragma unroll
    for (int m = 0; m < TM; m++) {
        int grow = block_row + tr * TM + m;
        if (grow >= nrows) continue;
        #pragma unroll
        for (int n = 0; n < TN; n++) {
            int c = tc * TN + n;
            float v = acc[m][n] + bias[c];
            if (do_relu) v = fmaxf(v, 0.0f);
            out[(size_t)grow * HH + c] = v;
        }
    }
}

// ---------------- pooling: batch is sorted -> binary-search boundaries ------
__global__ void graph_starts_kernel(const int* __restrict__ batch, int* __restrict__ start) {
    int b = blockIdx.x * blockDim.x + threadIdx.x;
    if (b > GG) return;
    if (b == GG) { start[GG] = NN; return; }
    int lo = 0, hi = NN;
    while (lo < hi) {
        int mid = (lo + hi) >> 1;
        if (batch[mid] < b) lo = mid + 1; else hi = mid;
    }
    start[b] = lo;
}

__global__ void pool_kernel(const float* __restrict__ x,
                            const int* __restrict__ start,
                            float* __restrict__ g) {
    int b = blockIdx.x;
    int s = start[b], e = start[b + 1];
    int lane = threadIdx.x;   // 0..31
    int w = threadIdx.y;      // 0..7
    float4 acc = make_float4(0, 0, 0, 0);
    for (int n = s + w; n < e; n += 8) {
        float4 v = *reinterpret_cast<const float4*>(x + (size_t)n * HH + lane * 4);
        acc = add4(acc, v);
    }
    __shared__ float4 sh[8][32];
    sh[w][lane] = acc;
    __syncthreads();
    if (w == 0) {
        float4 t = sh[0][lane];
        #pragma unroll
        for (int i = 1; i < 8; i++) t = add4(t, sh[i][lane]);
        *reinterpret_cast<float4*>(g + (size_t)b * HH + lane * 4) = t;
    }
}

// ---------------- final MLP: out[b] = relu(g@W1+b1)@W2 + b2 ----------------
__global__ void mlp_kernel(const float* __restrict__ g,
                           const float* __restrict__ W1,
                           const float* __restrict__ b1,
                           const float* __restrict__ W2,
                           const float* __restrict__ b2,
                           float* __restrict__ out) {
    int b = blockIdx.x;
    int t = threadIdx.x;   // 0..127
    __shared__ float gs[HH];
    gs[t] = g[(size_t)b * HH + t];
    __syncthreads();
    float acc = 0.0f;
    #pragma unroll 8
    for (int k = 0; k < HH; k++)
        acc = fmaf(gs[k], W1[(size_t)k * HH + t], acc);
    float h = fmaxf(acc + b1[t], 0.0f);
    float p = h * W2[t];
    #pragma unroll
    for (int off = 16; off > 0; off >>= 1)
        p += __shfl_xor_sync(0xFFFFFFFFu, p, off);
    __shared__ float ws[4];
    if ((t & 31) == 0) ws[t >> 5] = p;
    __syncthreads();
    if (t == 0) out[b] = ws[0] + ws[1] + ws[2] + ws[3] + b2[0];
}

// ---------------- launch ----------------
extern "C" void kernel_launch(void* const* d_in, const int* in_sizes, int n_in,
                              void* d_out, int out_size) {
    const int*   z     = (const int*)d_in[0];
    const int*   ei    = (const int*)d_in[1];    // [2,E] row-major: src then dst
    const int*   batch = (const int*)d_in[2];
    const float* z_emb = (const float*)d_in[3];
    const float* Wl[3] = {(const float*)d_in[4], (const float*)d_in[7], (const float*)d_in[10]};
    const float* bl[3] = {(const float*)d_in[5], (const float*)d_in[8], (const float*)d_in[11]};
    const float* Wr[3] = {(const float*)d_in[6], (const float*)d_in[9], (const float*)d_in[12]};
    const float* W1 = (const float*)d_in[13];
    const float* b1 = (const float*)d_in[14];
    const float* W2 = (const float*)d_in[15];
    const float* b2 = (const float*)d_in[16];
    float* out = (float*)d_out;

    float *x, *y, *agg, *deginv, *g;
    int *count, *rowptr, *cursor, *csrsrc, *start, *partial;
    cudaGetSymbolAddress((void**)&x,      d_x);
    cudaGetSymbolAddress((void**)&y,      d_y);
    cudaGetSymbolAddress((void**)&agg,    d_agg);
    cudaGetSymbolAddress((void**)&deginv, d_deginv);
    cudaGetSymbolAddress((void**)&g,      d_g);
    cudaGetSymbolAddress((void**)&count,  d_count);
    cudaGetSymbolAddress((void**)&rowptr, d_rowptr);
    cudaGetSymbolAddress((void**)&cursor, d_cursor);
    cudaGetSymbolAddress((void**)&csrsrc, d_csrsrc);
    cudaGetSymbolAddress((void**)&start,  d_start);
    cudaGetSymbolAddress((void**)&partial,d_partial);

    const int* src = ei;
    const int* dst = ei + EE;

    embed_kernel<<<(NN * 32 + 255) / 256, 256>>>(z, z_emb, x);
    zero_count_kernel<<<(NN + 255) / 256, 256>>>(count);
    hist_kernel<<<(EE + 255) / 256, 256>>>(dst, count);
    scan_blocks_kernel<<<NBLK, 1024>>>(count, rowptr, partial);
    scan_partials_kernel<<<1, 32>>>(partial);
    scan_finalize_kernel<<<NBLK, 1024>>>(count, partial, rowptr, cursor, deginv);
    fill_csr_kernel<<<(EE + 255) / 256, 256>>>(src, dst, cursor, csrsrc);
    graph_starts_kernel<<<3, 256>>>(batch, start);

    float* cur = x;
    float* nxt = y;
    for (int l = 0; l < 3; l++) {
        aggregate_kernel<<<(NN + 7) / 8, dim3(32, 8)>>>(cur, rowptr, csrsrc, deginv, agg);
        sage_gemm_kernel<<<(NN + BM - 1) / BM, 256>>>(agg, cur, Wl[l], Wr[l], bl[l], nxt, NN, (l < 2) ? 1 : 0);
        float* tmp = cur; cur = nxt; nxt = tmp;
    }

    pool_kernel<<<GG, dim3(32, 8)>>>(cur, start, g);
    mlp_kernel<<<GG, 128>>>(g, W1, b1, W2, b2, out);
}

// round 5
// speedup vs baseline: 2.0078x; 1.7495x over previous
#include <cuda_runtime.h>
#include <cuda_bf16.h>
#include <cstdint>
#include <cstdio>

#define NN 50000
#define EE 800000
#define HH 128
#define GG 512
#define NBLK ((NN + 1023) / 1024)        // 49
#define GEMM_BLOCKS ((NN + 127) / 128)   // 391

// ---------------- device scratch (no allocations allowed) ----------------
__device__ float d_x[NN * HH];
__device__ float d_y[NN * HH];
__device__ float d_agg[NN * HH];
__device__ int   d_count[NN];
__device__ int   d_rowptr[NN + 1];
__device__ int   d_cursor[NN];
__device__ int   d_csrsrc[EE];
__device__ float d_deginv[NN];
__device__ int   d_start[GG + 1];
__device__ float d_g[GG * HH];
__device__ int   d_partial[64];
// transposed + bf16-split weights: [3 layers][128 n][256 k]
__device__ __nv_bfloat16 d_wthi[3 * 128 * 256];
__device__ __nv_bfloat16 d_wtlo[3 * 128 * 256];

// ---------------- helpers ----------------
__device__ __forceinline__ float4 add4(float4 a, float4 b) {
    return make_float4(a.x + b.x, a.y + b.y, a.z + b.z, a.w + b.w);
}
__device__ __forceinline__ uint32_t cvta_smem(const void* p) {
    uint32_t a;
    asm("{ .reg .u64 t; cvta.to.shared.u64 t, %1; cvt.u32.u64 %0, t; }" : "=r"(a) : "l"(p));
    return a;
}
__device__ __forceinline__ void ldsm4(uint32_t* r, uint32_t addr) {
    asm volatile("ldmatrix.sync.aligned.m8n8.x4.shared.b16 {%0,%1,%2,%3}, [%4];"
                 : "=r"(r[0]), "=r"(r[1]), "=r"(r[2]), "=r"(r[3]) : "r"(addr));
}
__device__ __forceinline__ void mma16816(float* c, const uint32_t* a, const uint32_t* b) {
    asm volatile(
        "mma.sync.aligned.m16n8k16.row.col.f32.bf16.bf16.f32 "
        "{%0,%1,%2,%3}, {%4,%5,%6,%7}, {%8,%9}, {%0,%1,%2,%3};"
        : "+f"(c[0]), "+f"(c[1]), "+f"(c[2]), "+f"(c[3])
        : "r"(a[0]), "r"(a[1]), "r"(a[2]), "r"(a[3]), "r"(b[0]), "r"(b[1]));
}

// ---------------- embedding gather ----------------
__global__ void embed_kernel(const int* __restrict__ z,
                             const float* __restrict__ z_emb,
                             float* __restrict__ x) {
    int idx = blockIdx.x * blockDim.x + threadIdx.x;
    if (idx >= NN * 32) return;
    int n  = idx >> 5;
    int c4 = idx & 31;
    int zn = z[n];
    const float4* src = reinterpret_cast<const float4*>(z_emb) + (size_t)zn * 32 + c4;
    reinterpret_cast<float4*>(x)[idx] = *src;
}

__global__ void zero_count_kernel(int* __restrict__ count) {
    int i = blockIdx.x * blockDim.x + threadIdx.x;
    if (i < NN) count[i] = 0;
}

__global__ void hist_kernel(const int* __restrict__ dst, int* __restrict__ count) {
    int e = blockIdx.x * blockDim.x + threadIdx.x;
    if (e < EE) atomicAdd(&count[dst[e]], 1);
}

// ---------------- parallel 3-phase scan ----------------
__global__ __launch_bounds__(1024)
void scan_blocks_kernel(const int* __restrict__ count,
                        int* __restrict__ rowptr,
                        int* __restrict__ partial) {
    __shared__ int warp_sums[32];
    int gid = blockIdx.x * 1024 + threadIdx.x;
    int lane = threadIdx.x & 31;
    int wid  = threadIdx.x >> 5;
    int v = (gid < NN) ? count[gid] : 0;
    int incl = v;
    #pragma unroll
    for (int off = 1; off < 32; off <<= 1) {
        int t = __shfl_up_sync(0xFFFFFFFFu, incl, off);
        if (lane >= off) incl += t;
    }
    if (lane == 31) warp_sums[wid] = incl;
    __syncthreads();
    if (wid == 0) {
        int ws = warp_sums[lane];
        #pragma unroll
        for (int off = 1; off < 32; off <<= 1) {
            int t = __shfl_up_sync(0xFFFFFFFFu, ws, off);
            if (lane >= off) ws += t;
        }
        warp_sums[lane] = ws;
    }
    __syncthreads();
    int excl = incl - v + (wid > 0 ? warp_sums[wid - 1] : 0);
    if (gid < NN) rowptr[gid] = excl;
    if (threadIdx.x == 1023) partial[blockIdx.x] = excl + v;
}

__global__ void scan_partials_kernel(int* __restrict__ partial) {
    int lane = threadIdx.x;
    int carry = 0;
    for (int base = 0; base < NBLK; base += 32) {
        int i = base + lane;
        int v = (i < NBLK) ? partial[i] : 0;
        int incl = v;
        #pragma unroll
        for (int off = 1; off < 32; off <<= 1) {
            int t = __shfl_up_sync(0xFFFFFFFFu, incl, off);
            if (lane >= off) incl += t;
        }
        if (i < NBLK) partial[i] = incl - v + carry;
        carry += __shfl_sync(0xFFFFFFFFu, incl, 31);
    }
}

__global__ __launch_bounds__(1024)
void scan_finalize_kernel(const int* __restrict__ count,
                          const int* __restrict__ partial,
                          int* __restrict__ rowptr,
                          int* __restrict__ cursor,
                          float* __restrict__ deginv) {
    int gid = blockIdx.x * 1024 + threadIdx.x;
    if (gid < NN) {
        int r = rowptr[gid] + partial[blockIdx.x];
        rowptr[gid] = r;
        cursor[gid] = r;
        deginv[gid] = 1.0f / (float)max(count[gid], 1);
    }
    if (gid == 0) rowptr[NN] = EE;
}

__global__ void fill_csr_kernel(const int* __restrict__ src,
                                const int* __restrict__ dst,
                                int* __restrict__ cursor,
                                int* __restrict__ csrsrc) {
    int e = blockIdx.x * blockDim.x + threadIdx.x;
    if (e >= EE) return;
    int d = dst[e];
    int pos = atomicAdd(&cursor[d], 1);
    csrsrc[pos] = src[e];
}

// ---------------- mean aggregation: warp per destination node ----------------
__global__ void aggregate_kernel(const float* __restrict__ x,
                                 const int* __restrict__ rowptr,
                                 const int* __restrict__ csrsrc,
                                 const float* __restrict__ deginv,
                                 float* __restrict__ out) {
    int node = blockIdx.x * blockDim.y + threadIdx.y;
    if (node >= NN) return;
    int lane = threadIdx.x;
    int beg = rowptr[node];
    int end = rowptr[node + 1];
    float4 a0 = make_float4(0, 0, 0, 0);
    float4 a1 = make_float4(0, 0, 0, 0);
    int j = beg;
    for (; j + 1 < end; j += 2) {
        int s0 = __ldg(&csrsrc[j]);
        int s1 = __ldg(&csrsrc[j + 1]);
        float4 v0 = *reinterpret_cast<const float4*>(x + (size_t)s0 * HH + lane * 4);
        float4 v1 = *reinterpret_cast<const float4*>(x + (size_t)s1 * HH + lane * 4);
        a0 = add4(a0, v0);
        a1 = add4(a1, v1);
    }
    if (j < end) {
        int s0 = __ldg(&csrsrc[j]);
        float4 v0 = *reinterpret_cast<const float4*>(x + (size_t)s0 * HH + lane * 4);
        a0 = add4(a0, v0);
    }
    float di = deginv[node];
    float4 acc = add4(a0, a1);
    acc.x *= di; acc.y *= di; acc.z *= di; acc.w *= di;
    *reinterpret_cast<float4*>(out + (size_t)node * HH + lane * 4) = acc;
}

// ---------------- weight transpose + bf16 split ----------------
// Wt[n][k] (k-contiguous, 256 wide): k<128 -> Wl[k][n], k>=128 -> Wr[k-128][n]
__global__ void wcvt_kernel(const float* __restrict__ Wl,
                            const float* __restrict__ Wr,
                            __nv_bfloat16* __restrict__ whi,
                            __nv_bfloat16* __restrict__ wlo) {
    int i = blockIdx.x * blockDim.x + threadIdx.x;   // 32768
    if (i >= 32768) return;
    int n = i >> 8;
    int k = i & 255;
    float v = (k < 128) ? Wl[(size_t)k * HH + n] : Wr[(size_t)(k - 128) * HH + n];
    __nv_bfloat16 h = __float2bfloat16(v);
    __nv_bfloat16 l = __float2bfloat16(v - __bfloat162float(h));
    whi[i] = h;
    wlo[i] = l;
}

// ---------------- HMMA SAGE GEMM -----------------------------------------
// y[128 x 128] = [agg | x](128 x 256) @ [Wl ; Wr](256 x 128) + bias (opt relu)
// bf16 hi/lo split: acc = Ahi*Whi + Ahi*Wlo + Alo*Whi
#define AST 72   // smem row stride in bf16 elements (144B: conflict-free ldmatrix)
#define SA_HI 0
#define SA_LO 18432
#define SW_HI 36864
#define SW_LO 55296
#define SM_BIAS 73728
#define GEMM_SMEM (73728 + 512)

__global__ __launch_bounds__(256)
void sage_mma_gemm_kernel(const float* __restrict__ A0,   // agg [N,128]
                          const float* __restrict__ A1,   // x   [N,128]
                          const __nv_bfloat16* __restrict__ wthi,  // [128][256]
                          const __nv_bfloat16* __restrict__ wtlo,
                          const float* __restrict__ bias,
                          float* __restrict__ out,
                          int nrows, int do_relu) {
    extern __shared__ char sm[];
    uint32_t sbase = cvta_smem(sm);
    float* bias_sm = (float*)(sm + SM_BIAS);

    int tid  = threadIdx.x;
    int lane = tid & 31;
    int wid  = tid >> 5;
    int warp_m = wid & 3;    // 4 warps along M (32 rows each)
    int warp_n = wid >> 2;   // 2 warps along N (64 cols each)
    int block_row = blockIdx.x * 128;

    if (tid < 128) bias_sm[tid] = bias[tid];

    // ldmatrix per-lane addressing
    int a_row  = warp_m * 32 + ((lane >> 3) & 1) * 8 + (lane & 7);
    int a_colb = (lane >> 4) * 8;
    int b_n    = warp_n * 64 + (lane >> 4) * 8 + (lane & 7);
    int b_kb   = ((lane >> 3) & 1) * 8;

    float acc[2][8][4];
    #pragma unroll
    for (int mf = 0; mf < 2; mf++)
        #pragma unroll
        for (int nf = 0; nf < 8; nf++)
            #pragma unroll
            for (int i = 0; i < 4; i++) acc[mf][nf][i] = 0.0f;

    for (int c = 0; c < 4; c++) {
        if (c > 0) __syncthreads();   // previous chunk compute done

        // --- stage A chunk: 128 rows x 64 k, fp32 -> hi/lo bf16 ---
        const float* Asrc = (c < 2) ? A0 : A1;
        int kc = (c & 1) * 64;
        #pragma unroll
        for (int it = 0; it < 8; it++) {
            int i  = tid + it * 256;        // 0..2047 float4s
            int r  = i >> 4;                // 0..127
            int k4 = (i & 15) * 4;          // 0..60
            float4 v = make_float4(0, 0, 0, 0);
            int grow = block_row + r;
            if (grow < nrows)
                v = *reinterpret_cast<const float4*>(Asrc + (size_t)grow * HH + kc + k4);
            __nv_bfloat16 h0 = __float2bfloat16(v.x);
            __nv_bfloat16 h1 = __float2bfloat16(v.y);
            __nv_bfloat16 h2 = __float2bfloat16(v.z);
            __nv_bfloat16 h3 = __float2bfloat16(v.w);
            __nv_bfloat16 l0 = __float2bfloat16(v.x - __bfloat162float(h0));
            __nv_bfloat16 l1 = __float2bfloat16(v.y - __bfloat162float(h1));
            __nv_bfloat16 l2 = __float2bfloat16(v.z - __bfloat162float(h2));
            __nv_bfloat16 l3 = __float2bfloat16(v.w - __bfloat162float(h3));
            uint32_t hp0 = (uint32_t)__bfloat16_as_ushort(h0) | ((uint32_t)__bfloat16_as_ushort(h1) << 16);
            uint32_t hp1 = (uint32_t)__bfloat16_as_ushort(h2) | ((uint32_t)__bfloat16_as_ushort(h3) << 16);
            uint32_t lp0 = (uint32_t)__bfloat16_as_ushort(l0) | ((uint32_t)__bfloat16_as_ushort(l1) << 16);
            uint32_t lp1 = (uint32_t)__bfloat16_as_ushort(l2) | ((uint32_t)__bfloat16_as_ushort(l3) << 16);
            uint32_t boff = (uint32_t)(r * AST + k4) * 2;
            *(uint2*)(sm + SA_HI + boff) = make_uint2(hp0, hp1);
            *(uint2*)(sm + SA_LO + boff) = make_uint2(lp0, lp1);
        }
        // --- stage W chunk: 128 n x 64 k, pre-split bf16 (uint4 = 8 bf16) ---
        #pragma unroll
        for (int it = 0; it < 4; it++) {
            int i  = tid + it * 256;        // 0..1023
            int n  = i >> 3;                // 0..127
            int k8 = (i & 7) * 8;           // 0..56
            size_t goff = (size_t)n * 256 + c * 64 + k8;
            uint32_t boff = (uint32_t)(n * AST + k8) * 2;
            *(uint4*)(sm + SW_HI + boff) = *(const uint4*)(wthi + goff);
            *(uint4*)(sm + SW_LO + boff) = *(const uint4*)(wtlo + goff);
        }
        __syncthreads();

        // --- compute: 4 k16-steps ---
        #pragma unroll
        for (int ks = 0; ks < 4; ks++) {
            uint32_t ah[2][4], al[2][4];
            #pragma unroll
            for (int mf = 0; mf < 2; mf++) {
                uint32_t off = (uint32_t)((a_row + mf * 16) * AST + ks * 16 + a_colb) * 2;
                ldsm4(ah[mf], sbase + SA_HI + off);
                ldsm4(al[mf], sbase + SA_LO + off);
            }
            uint32_t bh[4][4], bl[4][4];
            #pragma unroll
            for (int ng = 0; ng < 4; ng++) {
                uint32_t off = (uint32_t)((b_n + ng * 16) * AST + ks * 16 + b_kb) * 2;
                ldsm4(bh[ng], sbase + SW_HI + off);
                ldsm4(bl[ng], sbase + SW_LO + off);
            }
            #pragma unroll
            for (int mf = 0; mf < 2; mf++) {
                #pragma unroll
                for (int nf = 0; nf < 8; nf++)
                    mma16816(acc[mf][nf], ah[mf], &bh[nf >> 1][(nf & 1) * 2]);
                #pragma unroll
                for (int nf = 0; nf < 8; nf++)
                    mma16816(acc[mf][nf], ah[mf], &bl[nf >> 1][(nf & 1) * 2]);
                #pragma unroll
                for (int nf = 0; nf < 8; nf++)
                    mma16816(acc[mf][nf], al[mf], &bh[nf >> 1][(nf & 1) * 2]);
            }
        }
    }

    // --- epilogue: bias + relu, float2 stores from accumulator fragments ---
    #pragma unroll
    for (int mf = 0; mf < 2; mf++) {
        int r0 = block_row + warp_m * 32 + mf * 16 + (lane >> 2);
        #pragma unroll
        for (int nf = 0; nf < 8; nf++) {
            int col = warp_n * 64 + nf * 8 + (lane & 3) * 2;
            float2 v0 = make_float2(acc[mf][nf][0] + bias_sm[col],
                                    acc[mf][nf][1] + bias_sm[col + 1]);
            float2 v1 = make_float2(acc[mf][nf][2] + bias_sm[col],
                                    acc[mf][nf][3] + bias_sm[col + 1]);
            if (do_relu) {
                v0.x = fmaxf(v0.x, 0.0f); v0.y = fmaxf(v0.y, 0.0f);
                v1.x = fmaxf(v1.x, 0.0f); v1.y = fmaxf(v1.y, 0.0f);
            }
            if (r0 < nrows)
                *reinterpret_cast<float2*>(out + (size_t)r0 * HH + col) = v0;
            if (r0 + 8 < nrows)
                *reinterpret_cast<float2*>(out + (size_t)(r0 + 8) * HH + col) = v1;
        }
    }
}

// ---------------- pooling ----------------
__global__ void graph_starts_kernel(const int* __restrict__ batch, int* __restrict__ start) {
    int b = blockIdx.x * blockDim.x + threadIdx.x;
    if (b > GG) return;
    if (b == GG) { start[GG] = NN; return; }
    int lo = 0, hi = NN;
    while (lo < hi) {
        int mid = (lo + hi) >> 1;
        if (batch[mid] < b) lo = mid + 1; else hi = mid;
    }
    start[b] = lo;
}

__global__ void pool_kernel(const float* __restrict__ x,
                            const int* __restrict__ start,
                            float* __restrict__ g) {
    int b = blockIdx.x;
    int s = start[b], e = start[b + 1];
    int lane = threadIdx.x;
    int w = threadIdx.y;
    float4 acc = make_float4(0, 0, 0, 0);
    for (int n = s + w; n < e; n += 8) {
        float4 v = *reinterpret_cast<const float4*>(x + (size_t)n * HH + lane * 4);
        acc = add4(acc, v);
    }
    __shared__ float4 sh[8][32];
    sh[w][lane] = acc;
    __syncthreads();
    if (w == 0) {
        float4 t = sh[0][lane];
        #pragma unroll
        for (int i = 1; i < 8; i++) t = add4(t, sh[i][lane]);
        *reinterpret_cast<float4*>(g + (size_t)b * HH + lane * 4) = t;
    }
}

// ---------------- final MLP ----------------
__global__ void mlp_kernel(const float* __restrict__ g,
                           const float* __restrict__ W1,
                           const float* __restrict__ b1,
                           const float* __restrict__ W2,
                           const float* __restrict__ b2,
                           float* __restrict__ out) {
    int b = blockIdx.x;
    int t = threadIdx.x;
    __shared__ float gs[HH];
    gs[t] = g[(size_t)b * HH + t];
    __syncthreads();
    float acc = 0.0f;
    #pragma unroll 8
    for (int k = 0; k < HH; k++)
        acc = fmaf(gs[k], W1[(size_t)k * HH + t], acc);
    float h = fmaxf(acc + b1[t], 0.0f);
    float p = h * W2[t];
    #pragma unroll
    for (int off = 16; off > 0; off >>= 1)
        p += __shfl_xor_sync(0xFFFFFFFFu, p, off);
    __shared__ float ws[4];
    if ((t & 31) == 0) ws[t >> 5] = p;
    __syncthreads();
    if (t == 0) out[b] = ws[0] + ws[1] + ws[2] + ws[3] + b2[0];
}

// ---------------- launch ----------------
extern "C" void kernel_launch(void* const* d_in, const int* in_sizes, int n_in,
                              void* d_out, int out_size) {
    const int*   z     = (const int*)d_in[0];
    const int*   ei    = (const int*)d_in[1];
    const int*   batch = (const int*)d_in[2];
    const float* z_emb = (const float*)d_in[3];
    const float* Wl[3] = {(const float*)d_in[4], (const float*)d_in[7], (const float*)d_in[10]};
    const float* bl[3] = {(const float*)d_in[5], (const float*)d_in[8], (const float*)d_in[11]};
    const float* Wr[3] = {(const float*)d_in[6], (const float*)d_in[9], (const float*)d_in[12]};
    const float* W1 = (const float*)d_in[13];
    const float* b1 = (const float*)d_in[14];
    const float* W2 = (const float*)d_in[15];
    const float* b2 = (const float*)d_in[16];
    float* out = (float*)d_out;

    float *x, *y, *agg, *deginv, *g;
    int *count, *rowptr, *cursor, *csrsrc, *start, *partial;
    __nv_bfloat16 *wthi, *wtlo;
    cudaGetSymbolAddress((void**)&x,      d_x);
    cudaGetSymbolAddress((void**)&y,      d_y);
    cudaGetSymbolAddress((void**)&agg,    d_agg);
    cudaGetSymbolAddress((void**)&deginv, d_deginv);
    cudaGetSymbolAddress((void**)&g,      d_g);
    cudaGetSymbolAddress((void**)&count,  d_count);
    cudaGetSymbolAddress((void**)&rowptr, d_rowptr);
    cudaGetSymbolAddress((void**)&cursor, d_cursor);
    cudaGetSymbolAddress((void**)&csrsrc, d_csrsrc);
    cudaGetSymbolAddress((void**)&start,  d_start);
    cudaGetSymbolAddress((void**)&partial,d_partial);
    cudaGetSymbolAddress((void**)&wthi,   d_wthi);
    cudaGetSymbolAddress((void**)&wtlo,   d_wtlo);

    cudaFuncSetAttribute(sage_mma_gemm_kernel,
                         cudaFuncAttributeMaxDynamicSharedMemorySize, GEMM_SMEM);

    const int* src = ei;
    const int* dst = ei + EE;

    embed_kernel<<<(NN * 32 + 255) / 256, 256>>>(z, z_emb, x);
    zero_count_kernel<<<(NN + 255) / 256, 256>>>(count);
    hist_kernel<<<(EE + 255) / 256, 256>>>(dst, count);
    scan_blocks_kernel<<<NBLK, 1024>>>(count, rowptr, partial);
    scan_partials_kernel<<<1, 32>>>(partial);
    scan_finalize_kernel<<<NBLK, 1024>>>(count, partial, rowptr, cursor, deginv);
    fill_csr_kernel<<<(EE + 255) / 256, 256>>>(src, dst, cursor, csrsrc);
    graph_starts_kernel<<<3, 256>>>(batch, start);
    for (int l = 0; l < 3; l++)
        wcvt_kernel<<<128, 256>>>(Wl[l], Wr[l],
                                  wthi + (size_t)l * 32768, wtlo + (size_t)l * 32768);

    float* cur = x;
    float* nxt = y;
    for (int l = 0; l < 3; l++) {
        aggregate_kernel<<<(NN + 7) / 8, dim3(32, 8)>>>(cur, rowptr, csrsrc, deginv, agg);
        sage_mma_gemm_kernel<<<GEMM_BLOCKS, 256, GEMM_SMEM>>>(
            agg, cur, wthi + (size_t)l * 32768, wtlo + (size_t)l * 32768,
            bl[l], nxt, NN, (l < 2) ? 1 : 0);
        float* tmp = cur; cur = nxt; nxt = tmp;
    }

    pool_kernel<<<GG, dim3(32, 8)>>>(cur, start, g);
    mlp_kernel<<<GG, 128>>>(g, W1, b1, W2, b2, out);
}